// round 14
// baseline (speedup 1.0000x reference)
#include <cuda_runtime.h>
#include <math.h>

#define Bn 8
#define Tn 512
#define Dn 1024
#define Rn 4
#define Vn 2048
#define Nn (Vn*Rn*Rn)   // 32768 columns of w_vocab
#define TC 32            // t-chunks (one block per (tc,b))
#define KS 8             // split-K factor for core GEMM
#define DKS (Dn/KS)      // 128 d-rows per split
#define DH (DKS/2)       // 64 d-rows per half (intra-block split)
#define DB 8             // d-batch depth (LDG.128 MLP)

// ---------------- scratch (no allocations allowed) ----------------
__device__ float g_xmean[Bn*Dn];          // [b][d] — atomically accumulated, pre-scaled
__device__ float g_core[Bn*Nn];           // accumulated core (1 MB)
__device__ float g_alpha[Bn*Rn];
__device__ float g_beta[Bn*Rn];

// ---------------- f32x2 helpers ----------------
__device__ __forceinline__ unsigned long long packx2(float s) {
    unsigned long long r;
    unsigned int u = __float_as_uint(s);
    asm("mov.b64 %0, {%1, %1};" : "=l"(r) : "r"(u));
    return r;
}
__device__ __forceinline__ void ffma2(unsigned long long& d,
                                      unsigned long long a,
                                      unsigned long long b) {
    asm("fma.rn.f32x2 %0, %1, %2, %0;" : "+l"(d) : "l"(a), "l"(b));
}
__device__ __forceinline__ float2 unpack2(unsigned long long v) {
    unsigned int lo, hi;
    asm("mov.b64 {%0, %1}, %2;" : "=r"(lo), "=r"(hi) : "l"(v));
    return make_float2(__uint_as_float(lo), __uint_as_float(hi));
}

// ---------------- K1: partial sums -> atomic xmean + zero g_core/out ----------------
// grid 256 (block = tc*8 + b), 512 threads: 256 d-threads x 2 t-halves (8 rows each).
// smem-combine halves, then 256 atomicAdds of pre-scaled sums into g_xmean.
__global__ void __launch_bounds__(512) k_partial(const float* __restrict__ x,
                                                 float* __restrict__ out) {
    __shared__ float4 sbuf[256];         // half-1 partials
    int bid = blockIdx.x;
    int tc = bid >> 3, b = bid & 7;
    int th = threadIdx.x;
    int half = th >> 8;                  // 0/1
    int dt = th & 255;                   // d-thread
    int d4 = dt * 4;

    const float* p = x + ((size_t)(b * Tn) + tc * (Tn/TC) + half * 8) * Dn + d4;
    float4 acc = make_float4(0.f, 0.f, 0.f, 0.f);
    #pragma unroll
    for (int t = 0; t < 8; t++) {
        float4 v = *(const float4*)(p + (size_t)t * Dn);
        acc.x += v.x; acc.y += v.y; acc.z += v.z; acc.w += v.w;
    }

    if (half == 1) sbuf[dt] = acc;
    __syncthreads();
    if (half == 0) {
        float4 o = sbuf[dt];
        const float sc = 1.0f / (float)Tn;
        float* xm = g_xmean + b * Dn + d4;
        atomicAdd(xm + 0, (acc.x + o.x) * sc);
        atomicAdd(xm + 1, (acc.y + o.y) * sc);
        atomicAdd(xm + 2, (acc.z + o.z) * sc);
        atomicAdd(xm + 3, (acc.w + o.w) * sc);
    }

    // zero g_core: 131072 float2 across 256 blocks x 512 threads
    int i2 = bid * 512 + th;
    *(float2*)&g_core[i2 * 2] = make_float2(0.f, 0.f);
    if (bid == 0 && th == 0) out[0] = 0.f;
}

// ---------------- K2: split-K core GEMM (f32x2, atomic epilogue) + alpha/beta ----------------
// grid (65, KS). blocks x<64: GEMM tile; x==64,y<2: alpha/beta.
__global__ void __launch_bounds__(256) k_gemm(const float* __restrict__ wv,
                                              const float* __restrict__ wa,
                                              const float* __restrict__ wb) {
    if (blockIdx.x == 64) {
        if (blockIdx.y >= 2) return;
        int mat = blockIdx.y;
        int o = threadIdx.x >> 3;      // 32 outputs
        int l8 = threadIdx.x & 7;
        int b = o >> 2, r = o & 3;
        const float* wm = mat ? wb : wa;
        const float* xb = g_xmean + b * Dn;
        float s = 0.f;
        #pragma unroll
        for (int j = 0; j < 128; j++) {
            int d = l8 + j * 8;
            s = fmaf(xb[d], __ldg(&wm[d * Rn + r]), s);
        }
        s += __shfl_down_sync(0xffffffffu, s, 4, 8);
        s += __shfl_down_sync(0xffffffffu, s, 2, 8);
        s += __shfl_down_sync(0xffffffffu, s, 1, 8);
        if (l8 == 0) {
            if (mat) g_beta[b * Rn + r] = s;
            else     g_alpha[b * Rn + r] = s;
        }
        return;
    }

    __shared__ float xs[DKS * Bn];       // xs[dd*8 + b], 4 KB
    __shared__ float4 red[128 * 8];      // 16 KB combine buffer
    int ks = blockIdx.y;
    int dbase = ks * DKS;
    for (int i = threadIdx.x; i < Bn * DKS; i += 256) {
        int b = i >> 7, dd = i & (DKS-1);
        xs[dd * 8 + b] = g_xmean[b * Dn + dbase + dd];
    }
    __syncthreads();

    int dh = threadIdx.x >> 7;           // 0/1 d-half
    int nt = threadIdx.x & 127;          // n-thread
    int n = (blockIdx.x * 128 + nt) * 4; // base of 4 columns
    int dho = dh * DH;

    unsigned long long acc2[4][4];
    #pragma unroll
    for (int p = 0; p < 4; p++)
        #pragma unroll
        for (int c = 0; c < 4; c++) acc2[p][c] = 0ull;

    const float* w = wv + (size_t)(dbase + dho) * Nn + n;
    #pragma unroll 1
    for (int du = 0; du < DH; du += DB) {
        float4 wr[DB];
        #pragma unroll
        for (int u = 0; u < DB; u++)
            wr[u] = __ldcs((const float4*)(w + (size_t)(du + u) * Nn));
        #pragma unroll
        for (int u = 0; u < DB; u++) {
            int dd = dho + du + u;
            ulonglong2 xp01 = *(const ulonglong2*)&xs[dd * 8];
            ulonglong2 xp23 = *(const ulonglong2*)&xs[dd * 8 + 4];
            float4 w4 = wr[u];
            unsigned long long ww0 = packx2(w4.x);
            unsigned long long ww1 = packx2(w4.y);
            unsigned long long ww2 = packx2(w4.z);
            unsigned long long ww3 = packx2(w4.w);
            ffma2(acc2[0][0], xp01.x, ww0); ffma2(acc2[0][1], xp01.x, ww1);
            ffma2(acc2[0][2], xp01.x, ww2); ffma2(acc2[0][3], xp01.x, ww3);
            ffma2(acc2[1][0], xp01.y, ww0); ffma2(acc2[1][1], xp01.y, ww1);
            ffma2(acc2[1][2], xp01.y, ww2); ffma2(acc2[1][3], xp01.y, ww3);
            ffma2(acc2[2][0], xp23.x, ww0); ffma2(acc2[2][1], xp23.x, ww1);
            ffma2(acc2[2][2], xp23.x, ww2); ffma2(acc2[2][3], xp23.x, ww3);
            ffma2(acc2[3][0], xp23.y, ww0); ffma2(acc2[3][1], xp23.y, ww1);
            ffma2(acc2[3][2], xp23.y, ww2); ffma2(acc2[3][3], xp23.y, ww3);
        }
    }

    float4 accf[8];
    #pragma unroll
    for (int p = 0; p < 4; p++) {
        float2 c0 = unpack2(acc2[p][0]);
        float2 c1 = unpack2(acc2[p][1]);
        float2 c2 = unpack2(acc2[p][2]);
        float2 c3 = unpack2(acc2[p][3]);
        accf[2*p+0] = make_float4(c0.x, c1.x, c2.x, c3.x);
        accf[2*p+1] = make_float4(c0.y, c1.y, c2.y, c3.y);
    }

    __syncthreads();
    if (dh == 1) {
        #pragma unroll
        for (int b = 0; b < 8; b++) red[nt * 8 + b] = accf[b];
    }
    __syncthreads();
    if (dh == 0) {
        #pragma unroll
        for (int b = 0; b < 8; b++) {
            float4 r = red[nt * 8 + b];
            float* o = g_core + (size_t)b * Nn + n;
            atomicAdd(o + 0, accf[b].x + r.x);
            atomicAdd(o + 1, accf[b].y + r.y);
            atomicAdd(o + 2, accf[b].z + r.z);
            atomicAdd(o + 3, accf[b].w + r.w);
        }
    }
}

// ---------------- K3: gather + normalize + shfl pair + tree + loss ----------------
#define MST 17   // smem matrix stride to break bank conflicts

__global__ void __launch_bounds__(512) k_tt(const int* __restrict__ labels,
                                            float* __restrict__ out) {
    __shared__ float bufA[256 * MST];
    __shared__ float bufB[128 * MST];
    int b = blockIdx.x;
    const float* cp = g_core + (size_t)b * Nn;
    int t = threadIdx.x;                // one matrix per thread

    // re-zero g_xmean for the next call (k_gemm already consumed it; 2 floats/thread)
    {
        int z = b * 512 + t;                     // 0..4095
        *(float2*)&g_xmean[z * 2] = make_float2(0.f, 0.f);
    }

    {
        int y = __ldg(&labels[b * Tn + t]);
        float4 r0 = __ldg((const float4*)(cp + 0 * (Vn*Rn) + y * 4));
        float4 r1 = __ldg((const float4*)(cp + 1 * (Vn*Rn) + y * 4));
        float4 r2 = __ldg((const float4*)(cp + 2 * (Vn*Rn) + y * 4));
        float4 r3 = __ldg((const float4*)(cp + 3 * (Vn*Rn) + y * 4));
        r0.x = fabsf(r0.x); r0.y = fabsf(r0.y); r0.z = fabsf(r0.z); r0.w = fabsf(r0.w);
        r1.x = fabsf(r1.x); r1.y = fabsf(r1.y); r1.z = fabsf(r1.z); r1.w = fabsf(r1.w);
        r2.x = fabsf(r2.x); r2.y = fabsf(r2.y); r2.z = fabsf(r2.z); r2.w = fabsf(r2.w);
        r3.x = fabsf(r3.x); r3.y = fabsf(r3.y); r3.z = fabsf(r3.z); r3.w = fabsf(r3.w);
        float4 s = make_float4(r0.x + r1.x + r2.x + r3.x,
                               r0.y + r1.y + r2.y + r3.y,
                               r0.z + r1.z + r2.z + r3.z,
                               r0.w + r1.w + r2.w + r3.w);
        float4 inv = make_float4(1.0f / s.x, 1.0f / s.y, 1.0f / s.z, 1.0f / s.w);
        float M[16];
        M[ 0] = r0.x * inv.x; M[ 1] = r0.y * inv.y; M[ 2] = r0.z * inv.z; M[ 3] = r0.w * inv.w;
        M[ 4] = r1.x * inv.x; M[ 5] = r1.y * inv.y; M[ 6] = r1.z * inv.z; M[ 7] = r1.w * inv.w;
        M[ 8] = r2.x * inv.x; M[ 9] = r2.y * inv.y; M[10] = r2.z * inv.z; M[11] = r2.w * inv.w;
        M[12] = r3.x * inv.x; M[13] = r3.y * inv.y; M[14] = r3.z * inv.z; M[15] = r3.w * inv.w;

        float N_[16];
        #pragma unroll
        for (int i = 0; i < 16; i++)
            N_[i] = __shfl_down_sync(0xffffffffu, M[i], 1);

        if ((t & 1) == 0) {
            float* dstM = bufA + (t >> 1) * MST;
            #pragma unroll
            for (int i = 0; i < 4; i++) {
                float c0 = 0.f, c1 = 0.f, c2 = 0.f, c3 = 0.f;
                #pragma unroll
                for (int l = 0; l < 4; l++) {
                    float a = N_[i * 4 + l];
                    c0 = fmaf(a, M[l * 4 + 0], c0);
                    c1 = fmaf(a, M[l * 4 + 1], c1);
                    c2 = fmaf(a, M[l * 4 + 2], c2);
                    c3 = fmaf(a, M[l * 4 + 3], c3);
                }
                dstM[i * 4 + 0] = c0; dstM[i * 4 + 1] = c1;
                dstM[i * 4 + 2] = c2; dstM[i * 4 + 3] = c3;
            }
        }
    }
    __syncthreads();

    float* src = bufA;
    float* dst = bufB;
    for (int nmat = 128; nmat >= 1; nmat >>= 1) {
        if (t < nmat) {
            const float* A0 = src + (2 * t) * MST;
            const float* A1 = src + (2 * t + 1) * MST;
            float* C = dst + t * MST;
            #pragma unroll
            for (int i = 0; i < 4; i++) {
                float c0 = 0.f, c1 = 0.f, c2 = 0.f, c3 = 0.f;
                #pragma unroll
                for (int l = 0; l < 4; l++) {
                    float a = A1[i * 4 + l];
                    c0 = fmaf(a, A0[l * 4 + 0], c0);
                    c1 = fmaf(a, A0[l * 4 + 1], c1);
                    c2 = fmaf(a, A0[l * 4 + 2], c2);
                    c3 = fmaf(a, A0[l * 4 + 3], c3);
                }
                C[i * 4 + 0] = c0; C[i * 4 + 1] = c1;
                C[i * 4 + 2] = c2; C[i * 4 + 3] = c3;
            }
        }
        __syncthreads();
        float* tmp = src; src = dst; dst = tmp;
    }

    if (t == 0) {
        const float* P = src;
        float a0 = fabsf(g_alpha[b * 4 + 0]);
        float a1 = fabsf(g_alpha[b * 4 + 1]);
        float a2 = fabsf(g_alpha[b * 4 + 2]);
        float a3 = fabsf(g_alpha[b * 4 + 3]);
        float sa = a0 + a1 + a2 + a3;
        float v0 = a0 / sa, v1 = a1 / sa, v2 = a2 / sa, v3 = a3 / sa;
        float w0 = P[ 0]*v0 + P[ 1]*v1 + P[ 2]*v2 + P[ 3]*v3;
        float w1 = P[ 4]*v0 + P[ 5]*v1 + P[ 6]*v2 + P[ 7]*v3;
        float w2 = P[ 8]*v0 + P[ 9]*v1 + P[10]*v2 + P[11]*v3;
        float w3 = P[12]*v0 + P[13]*v1 + P[14]*v2 + P[15]*v3;
        float b0 = fabsf(g_beta[b * 4 + 0]);
        float b1 = fabsf(g_beta[b * 4 + 1]);
        float b2 = fabsf(g_beta[b * 4 + 2]);
        float b3 = fabsf(g_beta[b * 4 + 3]);
        float sb = b0 + b1 + b2 + b3;
        float prob = (b0 * w0 + b1 * w1 + b2 * w2 + b3 * w3) / sb;
        atomicAdd(out, -logf(prob) * (1.0f / (float)Bn));
    }
}

// ---------------- launch ----------------
extern "C" void kernel_launch(void* const* d_in, const int* in_sizes, int n_in,
                              void* d_out, int out_size) {
    const float* x      = (const float*)d_in[0];  // [B,T,D] f32
    const int*   labels = (const int*)  d_in[1];  // [B,T] i32
    const float* wa     = (const float*)d_in[2];  // [D,R]
    const float* wb     = (const float*)d_in[3];  // [D,R]
    const float* wv     = (const float*)d_in[4];  // [D,V*R*R]

    k_partial<<<256, 512>>>(x, (float*)d_out);
    k_gemm<<<dim3(65, KS), 256>>>(wv, wa, wb);
    k_tt<<<Bn, 512>>>(labels, (float*)d_out);
}

// round 15
// speedup vs baseline: 1.1931x; 1.1931x over previous
#include <cuda_runtime.h>
#include <math.h>

#define Bn 8
#define Tn 512
#define Dn 1024
#define Rn 4
#define Vn 2048
#define Nn (Vn*Rn*Rn)   // 32768 columns of w_vocab
#define TC 64            // t-chunks (one block per (tc,b)), 8 rows each
#define KS 8             // split-K factor for core GEMM
#define DKS (Dn/KS)      // 128 d-rows per split
#define DH (DKS/2)       // 64 d-rows per half (intra-block split)
#define DB 8             // d-batch depth (LDG.128 MLP)

// ---------------- scratch (no allocations allowed) ----------------
__device__ float g_xmean[Bn*Dn];          // [b][d] — atomically accumulated, pre-scaled
__device__ float g_core[Bn*Nn];           // accumulated core (1 MB)
__device__ float g_alpha[Bn*Rn];
__device__ float g_beta[Bn*Rn];

// ---------------- f32x2 helpers ----------------
__device__ __forceinline__ unsigned long long packx2(float s) {
    unsigned long long r;
    unsigned int u = __float_as_uint(s);
    asm("mov.b64 %0, {%1, %1};" : "=l"(r) : "r"(u));
    return r;
}
__device__ __forceinline__ void ffma2(unsigned long long& d,
                                      unsigned long long a,
                                      unsigned long long b) {
    asm("fma.rn.f32x2 %0, %1, %2, %0;" : "+l"(d) : "l"(a), "l"(b));
}
__device__ __forceinline__ float2 unpack2(unsigned long long v) {
    unsigned int lo, hi;
    asm("mov.b64 {%0, %1}, %2;" : "=r"(lo), "=r"(hi) : "l"(v));
    return make_float2(__uint_as_float(lo), __uint_as_float(hi));
}

// ---------------- K1: partial sums -> atomic xmean + zero g_core/out ----------------
// grid 512 (block = tc*8 + b), 256 threads; 8 t-rows per thread.
__global__ void __launch_bounds__(256) k_partial(const float* __restrict__ x,
                                                 float* __restrict__ out) {
    int bid = blockIdx.x;
    int tc = bid >> 3, b = bid & 7;
    int d4 = threadIdx.x * 4;

    const float* p = x + ((size_t)(b * Tn) + tc * (Tn/TC)) * Dn + d4;
    float4 acc = make_float4(0.f, 0.f, 0.f, 0.f);
    #pragma unroll
    for (int t = 0; t < Tn/TC; t++) {
        float4 v = *(const float4*)(p + (size_t)t * Dn);
        acc.x += v.x; acc.y += v.y; acc.z += v.z; acc.w += v.w;
    }
    const float sc = 1.0f / (float)Tn;
    float* xm = g_xmean + b * Dn + d4;
    atomicAdd(xm + 0, acc.x * sc);
    atomicAdd(xm + 1, acc.y * sc);
    atomicAdd(xm + 2, acc.z * sc);
    atomicAdd(xm + 3, acc.w * sc);

    // zero g_core: 131072 float2 across 512 blocks x 256 threads
    int i2 = bid * 256 + threadIdx.x;
    *(float2*)&g_core[i2 * 2] = make_float2(0.f, 0.f);
    if (bid == 0 && threadIdx.x == 0) out[0] = 0.f;
}

// FMA block for one 8-deep w batch held in wrN (compile-time buffer name)
#define GEMM_COMPUTE(WRBUF, DU0)                                               \
    _Pragma("unroll")                                                          \
    for (int u = 0; u < DB; u++) {                                             \
        int dd = dho + (DU0) + u;                                              \
        ulonglong2 xp01 = *(const ulonglong2*)&xs[dd * 8];                     \
        ulonglong2 xp23 = *(const ulonglong2*)&xs[dd * 8 + 4];                 \
        float4 w4 = WRBUF[u];                                                  \
        unsigned long long ww0 = packx2(w4.x);                                 \
        unsigned long long ww1 = packx2(w4.y);                                 \
        unsigned long long ww2 = packx2(w4.z);                                 \
        unsigned long long ww3 = packx2(w4.w);                                 \
        ffma2(acc2[0][0], xp01.x, ww0); ffma2(acc2[0][1], xp01.x, ww1);        \
        ffma2(acc2[0][2], xp01.x, ww2); ffma2(acc2[0][3], xp01.x, ww3);        \
        ffma2(acc2[1][0], xp01.y, ww0); ffma2(acc2[1][1], xp01.y, ww1);        \
        ffma2(acc2[1][2], xp01.y, ww2); ffma2(acc2[1][3], xp01.y, ww3);        \
        ffma2(acc2[2][0], xp23.x, ww0); ffma2(acc2[2][1], xp23.x, ww1);        \
        ffma2(acc2[2][2], xp23.x, ww2); ffma2(acc2[2][3], xp23.x, ww3);        \
        ffma2(acc2[3][0], xp23.y, ww0); ffma2(acc2[3][1], xp23.y, ww1);        \
        ffma2(acc2[3][2], xp23.y, ww2); ffma2(acc2[3][3], xp23.y, ww3);        \
    }

// ---------------- K2: split-K core GEMM (f32x2, double-buffered) + alpha/beta ----------------
// grid (65, KS). blocks x<64: GEMM tile; x==64,y<2: alpha/beta.
__global__ void __launch_bounds__(256, 2) k_gemm(const float* __restrict__ wv,
                                                 const float* __restrict__ wa,
                                                 const float* __restrict__ wb) {
    if (blockIdx.x == 64) {
        if (blockIdx.y >= 2) return;
        int mat = blockIdx.y;
        int o = threadIdx.x >> 3;      // 32 outputs
        int l8 = threadIdx.x & 7;
        int b = o >> 2, r = o & 3;
        const float* wm = mat ? wb : wa;
        const float* xb = g_xmean + b * Dn;
        float s = 0.f;
        #pragma unroll
        for (int j = 0; j < 128; j++) {
            int d = l8 + j * 8;
            s = fmaf(xb[d], __ldg(&wm[d * Rn + r]), s);
        }
        s += __shfl_down_sync(0xffffffffu, s, 4, 8);
        s += __shfl_down_sync(0xffffffffu, s, 2, 8);
        s += __shfl_down_sync(0xffffffffu, s, 1, 8);
        if (l8 == 0) {
            if (mat) g_beta[b * Rn + r] = s;
            else     g_alpha[b * Rn + r] = s;
        }
        return;
    }

    __shared__ float xs[DKS * Bn];       // xs[dd*8 + b], 4 KB
    __shared__ float4 red[128 * 8];      // 16 KB combine buffer
    int ks = blockIdx.y;
    int dbase = ks * DKS;
    for (int i = threadIdx.x; i < Bn * DKS; i += 256) {
        int b = i >> 7, dd = i & (DKS-1);
        xs[dd * 8 + b] = g_xmean[b * Dn + dbase + dd];
    }
    __syncthreads();

    int dh = threadIdx.x >> 7;           // 0/1 d-half
    int nt = threadIdx.x & 127;          // n-thread
    int n = (blockIdx.x * 128 + nt) * 4; // base of 4 columns
    int dho = dh * DH;

    unsigned long long acc2[4][4];
    #pragma unroll
    for (int p = 0; p < 4; p++)
        #pragma unroll
        for (int c = 0; c < 4; c++) acc2[p][c] = 0ull;

    const float* w = wv + (size_t)(dbase + dho) * Nn + n;

    // register double-buffer: ping-pong 8-deep batches, next loads issue
    // before current FMA chain (compile-time buffer indices, no spill)
    float4 wr0[DB], wr1[DB];
    #pragma unroll
    for (int u = 0; u < DB; u++)
        wr0[u] = __ldcs((const float4*)(w + (size_t)u * Nn));

    #pragma unroll 1
    for (int du = 0; du < DH; du += 2 * DB) {
        // prefetch batch du+DB into wr1
        #pragma unroll
        for (int u = 0; u < DB; u++)
            wr1[u] = __ldcs((const float4*)(w + (size_t)(du + DB + u) * Nn));
        GEMM_COMPUTE(wr0, du)
        // prefetch batch du+2*DB into wr0 (if any)
        if (du + 2 * DB < DH) {
            #pragma unroll
            for (int u = 0; u < DB; u++)
                wr0[u] = __ldcs((const float4*)(w + (size_t)(du + 2 * DB + u) * Nn));
        }
        GEMM_COMPUTE(wr1, du + DB)
    }

    float4 accf[8];
    #pragma unroll
    for (int p = 0; p < 4; p++) {
        float2 c0 = unpack2(acc2[p][0]);
        float2 c1 = unpack2(acc2[p][1]);
        float2 c2 = unpack2(acc2[p][2]);
        float2 c3 = unpack2(acc2[p][3]);
        accf[2*p+0] = make_float4(c0.x, c1.x, c2.x, c3.x);
        accf[2*p+1] = make_float4(c0.y, c1.y, c2.y, c3.y);
    }

    __syncthreads();
    if (dh == 1) {
        #pragma unroll
        for (int b = 0; b < 8; b++) red[nt * 8 + b] = accf[b];
    }
    __syncthreads();
    if (dh == 0) {
        #pragma unroll
        for (int b = 0; b < 8; b++) {
            float4 r = red[nt * 8 + b];
            float* o = g_core + (size_t)b * Nn + n;
            atomicAdd(o + 0, accf[b].x + r.x);
            atomicAdd(o + 1, accf[b].y + r.y);
            atomicAdd(o + 2, accf[b].z + r.z);
            atomicAdd(o + 3, accf[b].w + r.w);
        }
    }
}

// ---------------- K3: gather + normalize + shfl pair + tree + loss ----------------
#define MST 17   // smem matrix stride to break bank conflicts

__global__ void __launch_bounds__(512) k_tt(const int* __restrict__ labels,
                                            float* __restrict__ out) {
    __shared__ float bufA[256 * MST];
    __shared__ float bufB[128 * MST];
    int b = blockIdx.x;
    const float* cp = g_core + (size_t)b * Nn;
    int t = threadIdx.x;                // one matrix per thread

    // re-zero g_xmean for the next call (k_gemm already consumed it)
    {
        int z = b * 512 + t;                     // 0..4095
        *(float2*)&g_xmean[z * 2] = make_float2(0.f, 0.f);
    }

    {
        int y = __ldg(&labels[b * Tn + t]);
        float4 r0 = __ldg((const float4*)(cp + 0 * (Vn*Rn) + y * 4));
        float4 r1 = __ldg((const float4*)(cp + 1 * (Vn*Rn) + y * 4));
        float4 r2 = __ldg((const float4*)(cp + 2 * (Vn*Rn) + y * 4));
        float4 r3 = __ldg((const float4*)(cp + 3 * (Vn*Rn) + y * 4));
        r0.x = fabsf(r0.x); r0.y = fabsf(r0.y); r0.z = fabsf(r0.z); r0.w = fabsf(r0.w);
        r1.x = fabsf(r1.x); r1.y = fabsf(r1.y); r1.z = fabsf(r1.z); r1.w = fabsf(r1.w);
        r2.x = fabsf(r2.x); r2.y = fabsf(r2.y); r2.z = fabsf(r2.z); r2.w = fabsf(r2.w);
        r3.x = fabsf(r3.x); r3.y = fabsf(r3.y); r3.z = fabsf(r3.z); r3.w = fabsf(r3.w);
        float4 s = make_float4(r0.x + r1.x + r2.x + r3.x,
                               r0.y + r1.y + r2.y + r3.y,
                               r0.z + r1.z + r2.z + r3.z,
                               r0.w + r1.w + r2.w + r3.w);
        float4 inv = make_float4(1.0f / s.x, 1.0f / s.y, 1.0f / s.z, 1.0f / s.w);
        float M[16];
        M[ 0] = r0.x * inv.x; M[ 1] = r0.y * inv.y; M[ 2] = r0.z * inv.z; M[ 3] = r0.w * inv.w;
        M[ 4] = r1.x * inv.x; M[ 5] = r1.y * inv.y; M[ 6] = r1.z * inv.z; M[ 7] = r1.w * inv.w;
        M[ 8] = r2.x * inv.x; M[ 9] = r2.y * inv.y; M[10] = r2.z * inv.z; M[11] = r2.w * inv.w;
        M[12] = r3.x * inv.x; M[13] = r3.y * inv.y; M[14] = r3.z * inv.z; M[15] = r3.w * inv.w;

        float N_[16];
        #pragma unroll
        for (int i = 0; i < 16; i++)
            N_[i] = __shfl_down_sync(0xffffffffu, M[i], 1);

        if ((t & 1) == 0) {
            float* dstM = bufA + (t >> 1) * MST;
            #pragma unroll
            for (int i = 0; i < 4; i++) {
                float c0 = 0.f, c1 = 0.f, c2 = 0.f, c3 = 0.f;
                #pragma unroll
                for (int l = 0; l < 4; l++) {
                    float a = N_[i * 4 + l];
                    c0 = fmaf(a, M[l * 4 + 0], c0);
                    c1 = fmaf(a, M[l * 4 + 1], c1);
                    c2 = fmaf(a, M[l * 4 + 2], c2);
                    c3 = fmaf(a, M[l * 4 + 3], c3);
                }
                dstM[i * 4 + 0] = c0; dstM[i * 4 + 1] = c1;
                dstM[i * 4 + 2] = c2; dstM[i * 4 + 3] = c3;
            }
        }
    }
    __syncthreads();

    float* src = bufA;
    float* dst = bufB;
    for (int nmat = 128; nmat >= 1; nmat >>= 1) {
        if (t < nmat) {
            const float* A0 = src + (2 * t) * MST;
            const float* A1 = src + (2 * t + 1) * MST;
            float* C = dst + t * MST;
            #pragma unroll
            for (int i = 0; i < 4; i++) {
                float c0 = 0.f, c1 = 0.f, c2 = 0.f, c3 = 0.f;
                #pragma unroll
                for (int l = 0; l < 4; l++) {
                    float a = A1[i * 4 + l];
                    c0 = fmaf(a, A0[l * 4 + 0], c0);
                    c1 = fmaf(a, A0[l * 4 + 1], c1);
                    c2 = fmaf(a, A0[l * 4 + 2], c2);
                    c3 = fmaf(a, A0[l * 4 + 3], c3);
                }
                C[i * 4 + 0] = c0; C[i * 4 + 1] = c1;
                C[i * 4 + 2] = c2; C[i * 4 + 3] = c3;
            }
        }
        __syncthreads();
        float* tmp = src; src = dst; dst = tmp;
    }

    if (t == 0) {
        const float* P = src;
        float a0 = fabsf(g_alpha[b * 4 + 0]);
        float a1 = fabsf(g_alpha[b * 4 + 1]);
        float a2 = fabsf(g_alpha[b * 4 + 2]);
        float a3 = fabsf(g_alpha[b * 4 + 3]);
        float sa = a0 + a1 + a2 + a3;
        float v0 = a0 / sa, v1 = a1 / sa, v2 = a2 / sa, v3 = a3 / sa;
        float w0 = P[ 0]*v0 + P[ 1]*v1 + P[ 2]*v2 + P[ 3]*v3;
        float w1 = P[ 4]*v0 + P[ 5]*v1 + P[ 6]*v2 + P[ 7]*v3;
        float w2 = P[ 8]*v0 + P[ 9]*v1 + P[10]*v2 + P[11]*v3;
        float w3 = P[12]*v0 + P[13]*v1 + P[14]*v2 + P[15]*v3;
        float b0 = fabsf(g_beta[b * 4 + 0]);
        float b1 = fabsf(g_beta[b * 4 + 1]);
        float b2 = fabsf(g_beta[b * 4 + 2]);
        float b3 = fabsf(g_beta[b * 4 + 3]);
        float sb = b0 + b1 + b2 + b3;
        float prob = (b0 * w0 + b1 * w1 + b2 * w2 + b3 * w3) / sb;
        atomicAdd(out, -logf(prob) * (1.0f / (float)Bn));
    }
}

// ---------------- launch ----------------
extern "C" void kernel_launch(void* const* d_in, const int* in_sizes, int n_in,
                              void* d_out, int out_size) {
    const float* x      = (const float*)d_in[0];  // [B,T,D] f32
    const int*   labels = (const int*)  d_in[1];  // [B,T] i32
    const float* wa     = (const float*)d_in[2];  // [D,R]
    const float* wb     = (const float*)d_in[3];  // [D,R]
    const float* wv     = (const float*)d_in[4];  // [D,V*R*R]

    k_partial<<<TC*Bn, 256>>>(x, (float*)d_out);
    k_gemm<<<dim3(65, KS), 256>>>(wv, wa, wb);
    k_tt<<<Bn, 512>>>(labels, (float*)d_out);
}